// round 14
// baseline (speedup 1.0000x reference)
#include <cuda_runtime.h>
#include <math.h>

// Problem constants
#define BATCH 64
#define SEQ   512
#define HID   1024
#define EMB   256
#define NCHAR 128

// Geometry: 128 persistent CTAs = 4 batch-groups (tb) x 32 j-tiles (tj).
// Each CTA = TWO concurrent half-CTAs (warps 0-3 = group A, 4-7 = group B),
// each half owning an independent 8-batch recurrence + its own 32-CTA barrier.
#define GRID     128
#define NTHREADS 256
#define BT       16      // batch rows per CTA (8 per half)
#define JT       32      // hidden rows per CTA

#define SH_STRIDE 20     // h tile row stride (words): [16 b][4 pad] — R6-proven
#define SP_STRIDE 34     // partial row stride (words)

#define SW_FLOATS (HID * JT)                    // 32768
#define SH_FLOATS (HID * SH_STRIDE)             // 20480 (shared: A cols 0-7, B cols 8-15)
#define SP_FLOATS_H (4 * 8 * SP_STRIDE)         // 1088 per half
#define SMEM_FLOATS (SW_FLOATS + SH_FLOATS + 2 * SP_FLOATS_H)
#define SMEM_BYTES  (SMEM_FLOATS * 4)           // 221,696 B

typedef unsigned long long u64;

// packed f32x2 (sm_100+): one SASS FFMA2 = 2 FMAs
#define FMA2(d, a, b)    asm("fma.rn.f32x2 %0, %1, %2, %0;" : "+l"(d) : "l"(a), "l"(b))
#define PACK2(d, lo, hi) asm("mov.b64 %0, {%1, %2};" : "=l"(d) : "f"(lo), "f"(hi))
#define BARH(id) asm volatile("bar.sync %0, 128;" :: "r"(id) : "memory")

// Device-global scratch
__device__ float g_U[NCHAR * HID];             // U = embeddings @ W_ih^T
__device__ float g_h[2][BATCH * HID];          // ping-pong hidden state
__device__ unsigned g_count[8 * 32];           // 8 group barriers (tb x half), 128B apart
__device__ volatile unsigned g_sense[8 * 32];  // sense; ends at 0 (514 phases/launch)

// ---------------------------------------------------------------------------
// 32-CTA group barrier for a HALF-CTA (128 threads) using a named barrier.
// One polling lane per CTA-half (the R6-proven low-contention pattern).
// ---------------------------------------------------------------------------
__device__ __forceinline__ void gbar_half(int ltid, unsigned* cnt,
                                          volatile unsigned* sns,
                                          unsigned s, int bid) {
    BARH(bid);                       // all 128 half-threads' stores issued
    if (ltid == 0) {
        __threadfence();
        if (atomicAdd(cnt, 1u) == 31u) {
            *cnt = 0;
            __threadfence();
            *sns = s;
        } else {
            while (*sns != s) { }
            __threadfence();
        }
    }
    BARH(bid);
}

// ---------------------------------------------------------------------------
// Kernel 0: U[c][j] = sum_e emb[c][e] * W_ih[j][e]
// ---------------------------------------------------------------------------
__global__ void u_kernel(const float* __restrict__ emb, const float* __restrict__ wih) {
    int gt   = blockIdx.x * blockDim.x + threadIdx.x;
    int warp = gt >> 5;
    int lane = gt & 31;
    int e0   = lane * 8;
    for (int i = 0; i < 32; i++) {
        int o = warp * 32 + i;
        int c = o >> 10;
        int j = o & 1023;
        const float4* ep = (const float4*)(emb + c * EMB + e0);
        const float4* wp = (const float4*)(wih + j * EMB + e0);
        float4 e1 = __ldg(ep),     e2 = __ldg(ep + 1);
        float4 w1 = __ldg(wp),     w2 = __ldg(wp + 1);
        float acc = e1.x*w1.x + e1.y*w1.y + e1.z*w1.z + e1.w*w1.w
                  + e2.x*w2.x + e2.y*w2.y + e2.z*w2.z + e2.w*w2.w;
        acc += __shfl_xor_sync(0xffffffffu, acc, 16);
        acc += __shfl_xor_sync(0xffffffffu, acc, 8);
        acc += __shfl_xor_sync(0xffffffffu, acc, 4);
        acc += __shfl_xor_sync(0xffffffffu, acc, 2);
        acc += __shfl_xor_sync(0xffffffffu, acc, 1);
        if (lane == 0) g_U[c * HID + j] = acc;
    }
}

// ---------------------------------------------------------------------------
// Persistent RNN scan, dual-pipeline CTA.
// Half h (warps h*4..h*4+3): 8 batches b0+h*8.., all 32 j's, own barrier group.
// Within a half: warp = k-quarter (kq), lane: jg = l&7 (4 j), ks = l>>3;
// klane = kq*4+ks; k = kk*16+klane (64 kk). Inner loop identical to the
// 4110us winner: 2x float4 h + 1x float4 W + 8 PACK + 16 FFMA2 per kk.
// ---------------------------------------------------------------------------
__global__ void __launch_bounds__(NTHREADS, 1) rnn_kernel(
    const int*   __restrict__ tids,
    const float* __restrict__ whh,
    const float* __restrict__ h0,
    const float* __restrict__ wproj,
    const float* __restrict__ bproj,
    float*       __restrict__ out)
{
    extern __shared__ float smem[];
    float* sW = smem;                         // [1024][32]  W slice, transposed
    float* sH = smem + SW_FLOATS;             // [1024][20]  h tile (A: cols 0-7, B: 8-15)

    const int tid = threadIdx.x;
    const int cta = blockIdx.x;
    const int tb  = cta >> 5;      // 0..3
    const int tj  = cta & 31;      // 0..31
    const int b0  = tb * BT;
    const int j0  = tj * JT;

    // one-time: W_hh slice transposed into SMEM (whole CTA)
    for (int idx = tid; idx < JT * HID; idx += NTHREADS) {
        int jj = idx >> 10;
        int k  = idx & 1023;
        sW[k * JT + jj] = whh[(j0 + jj) * HID + k];
    }
    // one-time: init h ping buffer (this CTA's 16b x 32j tile)
    for (int idx = tid; idx < BT * JT; idx += NTHREADS) {
        int bb = idx >> 5;
        int jj = idx & 31;
        g_h[0][(b0 + bb) * HID + (j0 + jj)] = h0[j0 + jj];
    }
    __syncthreads();               // W + init visible CTA-wide before halves diverge

    // ---- half-CTA decomposition ----
    const int half = tid >> 7;     // 0 = A (warps 0-3), 1 = B (warps 4-7)
    const int ltid = tid & 127;
    const int bid  = half + 1;     // named barrier id (0 reserved for syncthreads)
    const int grp  = tb * 2 + half;
    const int b0g  = b0 + half * 8;
    unsigned*          cnt = &g_count[grp * 32];
    volatile unsigned* sns = &g_sense[grp * 32];
    float* sP = smem + SW_FLOATS + SH_FLOATS + half * SP_FLOATS_H;

    unsigned bs = 1;
    gbar_half(ltid, cnt, sns, bs, bid);        // phase 1 (init visible group-wide)

    const int kq = ltid >> 5;      // warp-in-half = k quarter (0..3)
    const int l  = tid & 31;
    const int jg = l & 7;          // 4 j's
    const int ks = l >> 3;         // 0..3
    const int klane = kq * 4 + ks; // 0..15

    // GEMM pointers: half B reads columns 8-15 of each sH row
    const float* hptr0 = sH + klane * SH_STRIDE + half * 8;
    const float* wptr0 = sW + klane * JT + jg * 4;

    // staging: thread -> (bb 0..7 within half, kslot 0..15); 16 float4 each
    const int st_bb = ltid & 7;
    const int st_ks = ltid >> 3;   // 0..15

    // combine: thread -> (cjj, cbp): batches b0g+2cbp, b0g+2cbp+1; j = j0+cjj
    const int cjj = ltid & 31;
    const int cbp = ltid >> 5;     // 0..3
    const int cb0 = b0g + cbp * 2;

    for (int s = 0; s < SEQ; s++) {
        const int cur = s & 1;
        const int nxt = cur ^ 1;

        // prefetch epilogue operands (2-deep L2 chain) under staging + GEMM
        const int   c0 = __ldg(&tids[cb0 * SEQ + s]);
        const int   c1 = __ldg(&tids[(cb0 + 1) * SEQ + s]);
        const float u0 = __ldg(&g_U[c0 * HID + j0 + cjj]);
        const float u1 = __ldg(&g_U[c1 * HID + j0 + cjj]);

        // ---- stage this half's 8 batches: sH[k][half*8 + bb] ----
        {
            const float* hrow = g_h[cur] + (b0g + st_bb) * HID;
            float* shb = sH + half * 8 + st_bb;
            #pragma unroll 4
            for (int it = 0; it < 16; it++) {
                int k = (it * 16 + st_ks) * 4;
                float4 v = __ldcg((const float4*)(hrow + k));
                shb[(k + 0) * SH_STRIDE] = v.x;
                shb[(k + 1) * SH_STRIDE] = v.y;
                shb[(k + 2) * SH_STRIDE] = v.z;
                shb[(k + 3) * SH_STRIDE] = v.w;
            }
        }
        BARH(bid);

        // ---- packed f32x2 partial GEMM: 8b x 4j per lane, 64 k's ----
        u64 acc[4][4];
        #pragma unroll
        for (int bp = 0; bp < 4; bp++)
            #pragma unroll
            for (int j = 0; j < 4; j++) acc[bp][j] = 0ull;

        const float* hptr = hptr0;
        const float* wptr = wptr0;
        #pragma unroll 4
        for (int kk = 0; kk < 64; kk++) {
            float4 hA = *(const float4*)hptr;
            float4 hB = *(const float4*)(hptr + 4);
            float4 wv = *(const float4*)wptr;
            hptr += 16 * SH_STRIDE;
            wptr += 16 * JT;

            u64 hp[4], wd[4];
            PACK2(hp[0], hA.x, hA.y);  PACK2(hp[1], hA.z, hA.w);
            PACK2(hp[2], hB.x, hB.y);  PACK2(hp[3], hB.z, hB.w);
            PACK2(wd[0], wv.x, wv.x);  PACK2(wd[1], wv.y, wv.y);
            PACK2(wd[2], wv.z, wv.z);  PACK2(wd[3], wv.w, wv.w);

            #pragma unroll
            for (int bp = 0; bp < 4; bp++)
                #pragma unroll
                for (int j = 0; j < 4; j++)
                    FMA2(acc[bp][j], hp[bp], wd[j]);
        }

        // ---- intra-warp reduce over ks (lane bits 3,4), then stash partials ----
        #pragma unroll
        for (int bp = 0; bp < 4; bp++) {
            #pragma unroll
            for (int j = 0; j < 4; j++) {
                float lo = __uint_as_float((unsigned)(acc[bp][j] & 0xffffffffull));
                float hi = __uint_as_float((unsigned)(acc[bp][j] >> 32));
                lo += __shfl_xor_sync(0xffffffffu, lo, 8);
                hi += __shfl_xor_sync(0xffffffffu, hi, 8);
                lo += __shfl_xor_sync(0xffffffffu, lo, 16);
                hi += __shfl_xor_sync(0xffffffffu, hi, 16);
                if (ks == 0) {
                    *(float2*)(sP + (kq * 8 + jg) * SP_STRIDE + bp * 8 + j * 2)
                        = make_float2(lo, hi);
                }
            }
        }
        BARH(bid);

        // ---- combine 4 kq partials, add U, tanh, write next h ----
        {
            float slo = 0.f, shi = 0.f;
            #pragma unroll
            for (int q = 0; q < 4; q++) {
                float2 v = *(const float2*)(sP + (q * 8 + (cjj >> 2)) * SP_STRIDE
                                            + cbp * 8 + (cjj & 3) * 2);
                slo += v.x; shi += v.y;
            }
            float hn0 = tanhf(slo + u0);
            float hn1 = tanhf(shi + u1);
            __stcg(&g_h[nxt][cb0 * HID + j0 + cjj], hn0);
            __stcg(&g_h[nxt][(cb0 + 1) * HID + j0 + cjj], hn1);
        }

        bs ^= 1; gbar_half(ltid, cnt, sns, bs, bid);   // phases 2..513
    }

    bs ^= 1; gbar_half(ltid, cnt, sns, bs, bid);       // phase 514 (sense -> 0)
    __syncthreads();                                   // join halves

    // ---- final projection: out[b][c] = h_final[b] . W_proj[c] + b_proj[c] ----
    if (tid < 64) {
        const int bb = tid >> 2;
        const int cc = tid & 3;
        const int b  = b0 + bb;
        const int ch = tj * 4 + cc;
        const float* hp = g_h[0] + b * HID;
        const float* wp = wproj + ch * HID;
        float acc2 = 0.0f;
        #pragma unroll 4
        for (int k = 0; k < HID; k += 4) {
            float4 hv = __ldcg((const float4*)(hp + k));
            float4 wv = *(const float4*)(wp + k);
            acc2 += hv.x*wv.x + hv.y*wv.y + hv.z*wv.z + hv.w*wv.w;
        }
        out[b * NCHAR + ch] = acc2 + bproj[ch];
    }
}

// ---------------------------------------------------------------------------
// Launch: graph-capturable, no allocations, no syncs.
// Inputs: t, embeddings, W_ih, W_hh, h0, W_proj, b_proj.
// ---------------------------------------------------------------------------
extern "C" void kernel_launch(void* const* d_in, const int* in_sizes, int n_in,
                              void* d_out, int out_size)
{
    const int*   t     = (const int*)  d_in[0];
    const float* emb   = (const float*)d_in[1];
    const float* wih   = (const float*)d_in[2];
    const float* whh   = (const float*)d_in[3];
    const float* h0    = (const float*)d_in[4];
    const float* wproj = (const float*)d_in[5];
    const float* bproj = (const float*)d_in[6];
    float*       out   = (float*)d_out;

    cudaFuncSetAttribute(rnn_kernel, cudaFuncAttributeMaxDynamicSharedMemorySize, SMEM_BYTES);

    u_kernel<<<512, 256>>>(emb, wih);
    rnn_kernel<<<GRID, NTHREADS, SMEM_BYTES>>>(t, whh, h0, wproj, bproj, out);
}